// round 13
// baseline (speedup 1.0000x reference)
#include <cuda_runtime.h>
#include <cuda_bf16.h>

#define N_NODE   100000
#define N_REL    8
#define EMB      32
#define OUT      32
#define NE       1600000
#define BATCH    16384
#define H1       64
#define H2       32
#define H3       16
#define CAP      128   // fixed bucket capacity per node (P(deg>128) ~ 1e-50)

typedef unsigned long long ull;

// ---------------- scratch (static device globals; no allocation) ----------------
__device__ float  g_w[N_REL * EMB * OUT];               // relation weights
__device__ float  g_xh[(size_t)N_NODE * N_REL * OUT];   // 102.4 MB per-(node,rel) transform
__device__ float2 g_dsj[N_NODE * N_REL];                // {di, sj} per (node,rel)
__device__ float  g_h[N_NODE * OUT];                    // final node features (needed rows only)
__device__ int    g_need[N_NODE];
__device__ int    g_cntr[N_NODE];                       // bucket cursor / degree
__device__ int    g_nlist[N_NODE];                      // compact list of needed nodes
__device__ int    g_ebuf[(size_t)N_NODE * CAP];         // 51.2 MB fixed-stride buckets: src*8+t
__device__ int    g_ncnt;

// packed f32x2 ops (Blackwell)
__device__ __forceinline__ ull fma2(ull a, ull b, ull c) {
    ull d;
    asm("fma.rn.f32x2 %0, %1, %2, %3;" : "=l"(d) : "l"(a), "l"(b), "l"(c));
    return d;
}
__device__ __forceinline__ float fold2(ull a) {   // lo + hi of a packed f32x2
    float lo, hi;
    asm("mov.b64 {%0,%1}, %2;" : "=f"(lo), "=f"(hi) : "l"(a));
    return lo + hi;
}
__device__ __forceinline__ ull pack2(float lo, float hi) {
    ull d;
    asm("mov.b64 %0, {%1,%2};" : "=l"(d) : "f"(lo), "f"(hi));
    return d;
}

// ---------------- K0: fused basis GEMM (blocks 0..31) + scratch zeroing ----------------
__global__ void initbasis_k(const float* __restrict__ weight, const float* __restrict__ basis) {
    int b = blockIdx.x;
    int tid = threadIdx.x;
    if (b < 32) {
        int gid = b * 256 + tid;
        int r = gid >> 10, fo = gid & 1023;
        float acc = 0.f;
        #pragma unroll
        for (int k = 0; k < 30; k++)
            acc += __ldg(weight + r * 30 + k) * __ldg(basis + k * 1024 + fo);
        g_w[r * 1024 + fo] = acc;
        if (gid == 0) g_ncnt = 0;
    } else {
        int i = (b - 32) * 256 + tid;
        int stride = (gridDim.x - 32) * 256;
        for (int j = i; j < N_NODE; j += stride) { g_need[j] = 0; g_cntr[j] = 0; }
    }
}

// ---------------- K1: mark needed dst nodes + compact list ----------------
__global__ void mark_k(const int* __restrict__ users, const int* __restrict__ bundles) {
    int i = blockIdx.x * blockDim.x + threadIdx.x;
    if (i >= 2 * BATCH) return;
    int u = (i < BATCH) ? users[i] : bundles[i - BATCH];
    if (atomicExch(&g_need[u], 1) == 0) {
        int p = atomicAdd(&g_ncnt, 1);
        g_nlist[p] = u;
    }
}

// ---------------- K2: single-pass bucket fill ----------------
__global__ void fill_k(const int* __restrict__ ei, const int* __restrict__ et) {
    int e = blockIdx.x * 256 + threadIdx.x;
    if (e >= NE) return;
    int dst = ei[NE + e];
    if (!g_need[dst]) return;
    int pos = atomicAdd(&g_cntr[dst], 1);
    if (pos < CAP)
        g_ebuf[(size_t)dst * CAP + pos] = ei[e] * N_REL + et[e];
}

// ---------------- K3: xh + fused {di,sj}  (FFMA2 packed over f) ----------------
// Pack the REDUCTION dim: acc2 += {x[2q],x[2q+1]} * {w[2q][o],w[2q+1][o]}, fold at end.
// One LDS.64 of natural x feeds 2 FFMA2 -> halves smem crossbar lane-bytes.
__global__ void xh_k(const int* __restrict__ x_ids, const float* __restrict__ emb,
                     const float* __restrict__ att) {
    __shared__ float xs[128 * EMB];      // 16 KB natural layout
    __shared__ float swa1[N_REL * EMB];  // 1 KB w@att(:,0:32)   per (r,f)
    __shared__ float swa2[N_REL * EMB];  // 1 KB w@att(:,32:64)
    int tid = threadIdx.x;
    int n0 = blockIdx.x * 128;

    {   // per-block wa: thread=(r,f)
        int r = tid >> 5, f = tid & 31;
        const float4* wr = (const float4*)(g_w + (r * EMB + f) * OUT);
        const float* a1 = att + r * 64;
        const float* a2 = a1 + 32;
        float s1 = 0.f, s2 = 0.f;
        #pragma unroll
        for (int q = 0; q < 8; q++) {
            float4 wv = wr[q];
            s1 += wv.x * __ldg(a1 + 4 * q)     + wv.y * __ldg(a1 + 4 * q + 1)
                + wv.z * __ldg(a1 + 4 * q + 2) + wv.w * __ldg(a1 + 4 * q + 3);
            s2 += wv.x * __ldg(a2 + 4 * q)     + wv.y * __ldg(a2 + 4 * q + 1)
                + wv.z * __ldg(a2 + 4 * q + 2) + wv.w * __ldg(a2 + 4 * q + 3);
        }
        swa1[r * EMB + f] = s1;
        swa2[r * EMB + f] = s2;
    }

    for (int idx = tid; idx < 128 * EMB; idx += 256) {
        int nl = idx >> 5, f = idx & 31;
        int n = n0 + nl;
        xs[idx] = (n < N_NODE) ? emb[(size_t)x_ids[n] * EMB + f] : 0.f;
    }
    __syncthreads();

    int g   = tid >> 7;
    int sub = tid & 127;
    int r   = sub >> 4;
    int o2  = sub & 15;
    int oa  = 2 * o2;        // thread's two outputs: oa, oa+1

    // w packed over f-pairs for each of the two outputs
    ull wA[16], wB[16];
    {
        const float* wrow = g_w + r * EMB * OUT;
        #pragma unroll
        for (int q = 0; q < 16; q++) {
            wA[q] = pack2(wrow[(2 * q) * OUT + oa],     wrow[(2 * q + 1) * OUT + oa]);
            wB[q] = pack2(wrow[(2 * q) * OUT + oa + 1], wrow[(2 * q + 1) * OUT + oa + 1]);
        }
    }

    int gbase = n0 + g * 64;
    int cnt = N_NODE - gbase;
    if (cnt > 64) cnt = 64;
    // cnt is 64, 32, or <=0 (always even when positive)

    for (int i = 0; i < cnt; i += 2) {
        const ull* xp0 = (const ull*)(xs + ((g * 64 + i) << 5));
        const ull* xp1 = (const ull*)(xs + ((g * 64 + i + 1) << 5));
        ull a0 = 0ULL, a1 = 0ULL, b0 = 0ULL, b1 = 0ULL;
        #pragma unroll
        for (int q = 0; q < 16; q++) {
            ull x0 = xp0[q];
            a0 = fma2(x0, wA[q], a0);
            a1 = fma2(x0, wB[q], a1);
            ull x1 = xp1[q];
            b0 = fma2(x1, wA[q], b0);
            b1 = fma2(x1, wB[q], b1);
        }
        size_t base = (size_t)(gbase + i) * (N_REL * OUT) + r * OUT + oa;
        *(float2*)(g_xh + base)                = make_float2(fold2(a0), fold2(a1));
        *(float2*)(g_xh + base + N_REL * OUT)  = make_float2(fold2(b0), fold2(b1));
    }

    // fused {di,sj}: 4 relations per thread, packed over f-pairs
    int nl = tid >> 1;
    int rbase = (tid & 1) * 4;
    int n = n0 + nl;
    if (n < N_NODE) {
        const ull* xp = (const ull*)(xs + (nl << 5));
        ull xv[16];
        #pragma unroll
        for (int q = 0; q < 16; q++) xv[q] = xp[q];
        #pragma unroll
        for (int k = 0; k < 4; k++) {
            int rr = rbase + k;
            const ull* w1p = (const ull*)(swa1 + rr * EMB);
            const ull* w2p = (const ull*)(swa2 + rr * EMB);
            ull aD = 0ULL, aS = 0ULL;
            #pragma unroll
            for (int q = 0; q < 16; q++) {
                aD = fma2(xv[q], w1p[q], aD);
                aS = fma2(xv[q], w2p[q], aS);
            }
            g_dsj[(size_t)n * N_REL + rr] = make_float2(fold2(aD), fold2(aS));
        }
    }
}

// ---------------- K4: per-node aggregation, lane-parallel softmax, no smem RMW ----------------
__global__ void nodeagg_k(const int* __restrict__ x_ids, const float* __restrict__ emb,
                          const float* __restrict__ root, const float* __restrict__ bias) {
    __shared__ float sroot[EMB * OUT];   // 4 KB
    __shared__ int   sst[8][CAP];        // 4 KB  cached src*8+t
    __shared__ float sw[8][CAP];         // 4 KB  cached softmax weights

    int tid = threadIdx.x;
    int wid = tid >> 5, lane = tid & 31;
    for (int i = tid; i < EMB * OUT; i += 256) sroot[i] = root[i];
    __syncthreads();

    int widx = blockIdx.x * 8 + wid;
    if (widx >= g_ncnt) return;
    int n   = g_nlist[widx];
    int deg = g_cntr[n];
    if (deg > CAP) deg = CAP;
    const int* ebase = g_ebuf + (size_t)n * CAP;

    float dv = 0.f;
    if (lane < N_REL) dv = g_dsj[n * N_REL + lane].x;

    // ---- phase 1: lane-parallel ex + per-relation denominators ----
    float pden[N_REL];
    #pragma unroll
    for (int t8 = 0; t8 < N_REL; t8++) pden[t8] = 0.f;

    for (int c = 0; c < deg; c += 32) {
        int j = c + lane;
        bool v = (j < deg);
        int st = 0;
        float ex = 0.f;
        int t = 0;
        if (v) {
            st = __ldg(&ebase[j]);
            t = st & 7;
        }
        float di = __shfl_sync(0xffffffffu, dv, t);
        if (v) {
            float sj = __ldg(&((const float*)g_dsj)[2 * st + 1]);
            float s = di + sj;
            s = (s > 0.f) ? s : 0.2f * s;
            ex = __expf(s);
            sst[wid][j] = st;
            sw[wid][j] = ex;
        }
        #pragma unroll
        for (int t8 = 0; t8 < N_REL; t8++)
            pden[t8] += (v && t == t8) ? ex : 0.f;
    }

    float den[N_REL];
    #pragma unroll
    for (int t8 = 0; t8 < N_REL; t8++) {
        float s = pden[t8];
        #pragma unroll
        for (int o = 16; o > 0; o >>= 1) s += __shfl_xor_sync(0xffffffffu, s, o);
        den[t8] = s + 1e-16f;
    }

    for (int c = 0; c < deg; c += 32) {
        int j = c + lane;
        if (j < deg) {
            int t = sst[wid][j] & 7;
            float d = den[0];
            #pragma unroll
            for (int t8 = 1; t8 < N_REL; t8++) if (t == t8) d = den[t8];
            sw[wid][j] = sw[wid][j] / d;
        }
    }
    __syncwarp();

    // ---- phase 2: gather hj rows, weighted register accumulation ----
    float acc = 0.f;
    #pragma unroll 8
    for (int j = 0; j < deg; j++) {
        int stj  = sst[wid][j];
        float wj = sw[wid][j];
        acc += __ldg(&g_xh[(size_t)stj * OUT + lane]) * wj;
    }

    // ---- finalize: h = relu(acc + bias + x@root) ----
    acc += __ldg(&bias[lane]);
    float xv = __ldg(&emb[(size_t)x_ids[n] * EMB + lane]);
    #pragma unroll
    for (int f = 0; f < EMB; f++)
        acc += __shfl_sync(0xffffffffu, xv, f) * sroot[f * OUT + lane];
    g_h[n * OUT + lane] = fmaxf(acc, 0.f);
}

// ---------------- K5: MLP over (user,bundle) pairs ----------------
__global__ void mlp_k(const int* __restrict__ users, const int* __restrict__ bundles,
                      const float* __restrict__ W1, const float* __restrict__ b1,
                      const float* __restrict__ W2, const float* __restrict__ b2,
                      const float* __restrict__ W3, const float* __restrict__ b3,
                      const float* __restrict__ Wo, const float* __restrict__ bo,
                      float* __restrict__ out) {
    __shared__ float sW1[2 * OUT * H1];
    __shared__ float sW2[H1 * H2];
    __shared__ float sW3[H2 * H3];
    __shared__ float sWo[H3];
    __shared__ float sb1[H1], sb2[H2], sb3[H3];

    int tid = threadIdx.x;
    for (int i = tid; i < 2 * OUT * H1; i += 128) sW1[i] = W1[i];
    for (int i = tid; i < H1 * H2; i += 128) sW2[i] = W2[i];
    for (int i = tid; i < H2 * H3; i += 128) sW3[i] = W3[i];
    if (tid < H3) sWo[tid] = Wo[tid];
    if (tid < H1) sb1[tid] = b1[tid];
    if (tid < H2) sb2[tid] = b2[tid];
    if (tid < H3) sb3[tid] = b3[tid];
    __syncthreads();

    int b = blockIdx.x * 128 + tid;
    if (b >= BATCH) return;

    int nu = users[b], nb = bundles[b];
    float z[2 * OUT];
    const float4* hu = (const float4*)(g_h + (size_t)nu * OUT);
    const float4* hb = (const float4*)(g_h + (size_t)nb * OUT);
    #pragma unroll
    for (int k = 0; k < 8; k++) {
        float4 v = hu[k];
        z[4 * k] = v.x; z[4 * k + 1] = v.y; z[4 * k + 2] = v.z; z[4 * k + 3] = v.w;
    }
    #pragma unroll
    for (int k = 0; k < 8; k++) {
        float4 v = hb[k];
        z[32 + 4 * k] = v.x; z[32 + 4 * k + 1] = v.y; z[32 + 4 * k + 2] = v.z; z[32 + 4 * k + 3] = v.w;
    }

    float a1[H1];
    for (int j = 0; j < H1; j++) {
        float acc = sb1[j];
        #pragma unroll
        for (int k = 0; k < 2 * OUT; k++) acc += z[k] * sW1[k * H1 + j];
        a1[j] = fmaxf(acc, 0.f);
    }
    float a2[H2];
    for (int j = 0; j < H2; j++) {
        float acc = sb2[j];
        #pragma unroll
        for (int k = 0; k < H1; k++) acc += a1[k] * sW2[k * H2 + j];
        a2[j] = fmaxf(acc, 0.f);
    }
    float a3[H3];
    for (int j = 0; j < H3; j++) {
        float acc = sb3[j];
        #pragma unroll
        for (int k = 0; k < H2; k++) acc += a2[k] * sW3[k * H3 + j];
        a3[j] = fmaxf(acc, 0.f);
    }
    float o = __ldg(bo);
    #pragma unroll
    for (int k = 0; k < H3; k++) o += a3[k] * sWo[k];
    out[b] = o;
}

// ---------------- launch ----------------
extern "C" void kernel_launch(void* const* d_in, const int* in_sizes, int n_in,
                              void* d_out, int out_size) {
    const int*   x_ids      = (const int*)d_in[0];
    const int*   edge_index = (const int*)d_in[1];
    const int*   edge_type  = (const int*)d_in[2];
    const int*   users      = (const int*)d_in[3];
    const int*   bundles    = (const int*)d_in[4];
    const float* emb        = (const float*)d_in[5];
    const float* basis      = (const float*)d_in[6];
    const float* weight     = (const float*)d_in[7];
    const float* att        = (const float*)d_in[8];
    const float* root       = (const float*)d_in[9];
    const float* bias       = (const float*)d_in[10];
    const float* W1         = (const float*)d_in[11];
    const float* b1         = (const float*)d_in[12];
    const float* W2         = (const float*)d_in[13];
    const float* b2         = (const float*)d_in[14];
    const float* W3         = (const float*)d_in[15];
    const float* b3         = (const float*)d_in[16];
    const float* Wo         = (const float*)d_in[17];
    const float* bo         = (const float*)d_in[18];
    float* out = (float*)d_out;

    initbasis_k<<<32 + 256, 256>>>(weight, basis);                 // 0
    mark_k<<<(2 * BATCH + 255) / 256, 256>>>(users, bundles);      // 1
    fill_k<<<(NE + 255) / 256, 256>>>(edge_index, edge_type);      // 2
    xh_k<<<(N_NODE + 127) / 128, 256>>>(x_ids, emb, att);          // 3  <- profiled
    nodeagg_k<<<(2 * BATCH + 7) / 8, 256>>>(x_ids, emb, root, bias); // 4
    mlp_k<<<BATCH / 128, 128>>>(users, bundles,
                                W1, b1, W2, b2, W3, b3, Wo, bo, out); // 5
}

// round 14
// speedup vs baseline: 1.5381x; 1.5381x over previous
#include <cuda_runtime.h>
#include <cuda_bf16.h>

#define N_NODE   100000
#define N_REL    8
#define EMB      32
#define OUT      32
#define NE       1600000
#define BATCH    16384
#define H1       64
#define H2       32
#define H3       16
#define CAP      128   // fixed bucket capacity per node (P(deg>128) ~ 1e-50)

typedef unsigned long long ull;

// ---------------- scratch (static device globals; no allocation) ----------------
__device__ float  g_w[N_REL * EMB * OUT];        // relation weights w[r][f][o]
__device__ float2 g_dsj[N_NODE * N_REL];         // {di, sj} per (node,rel)
__device__ float  g_h[N_NODE * OUT];             // final node features (needed rows only)
__device__ int    g_need[N_NODE];
__device__ int    g_cntr[N_NODE];                // bucket cursor / degree
__device__ int    g_nlist[N_NODE];               // compact list of needed nodes
__device__ int    g_ebuf[(size_t)N_NODE * CAP];  // fixed-stride buckets: src*8+t
__device__ int    g_ncnt;

// packed f32x2 ops (Blackwell)
__device__ __forceinline__ ull fma2(ull a, ull b, ull c) {
    ull d;
    asm("fma.rn.f32x2 %0, %1, %2, %3;" : "=l"(d) : "l"(a), "l"(b), "l"(c));
    return d;
}
__device__ __forceinline__ float fold2(ull a) {
    float lo, hi;
    asm("mov.b64 {%0,%1}, %2;" : "=f"(lo), "=f"(hi) : "l"(a));
    return lo + hi;
}

// ---------------- K0: fused basis GEMM (blocks 0..31) + scratch zeroing ----------------
__global__ void initbasis_k(const float* __restrict__ weight, const float* __restrict__ basis) {
    int b = blockIdx.x;
    int tid = threadIdx.x;
    if (b < 32) {
        int gid = b * 256 + tid;
        int r = gid >> 10, fo = gid & 1023;
        float acc = 0.f;
        #pragma unroll
        for (int k = 0; k < 30; k++)
            acc += __ldg(weight + r * 30 + k) * __ldg(basis + k * 1024 + fo);
        g_w[r * 1024 + fo] = acc;
        if (gid == 0) g_ncnt = 0;
    } else {
        int i = (b - 32) * 256 + tid;
        int stride = (gridDim.x - 32) * 256;
        for (int j = i; j < N_NODE; j += stride) { g_need[j] = 0; g_cntr[j] = 0; }
    }
}

// ---------------- K1: mark needed dst nodes + compact list ----------------
__global__ void mark_k(const int* __restrict__ users, const int* __restrict__ bundles) {
    int i = blockIdx.x * blockDim.x + threadIdx.x;
    if (i >= 2 * BATCH) return;
    int u = (i < BATCH) ? users[i] : bundles[i - BATCH];
    if (atomicExch(&g_need[u], 1) == 0) {
        int p = atomicAdd(&g_ncnt, 1);
        g_nlist[p] = u;
    }
}

// ---------------- K2: single-pass bucket fill ----------------
__global__ void fill_k(const int* __restrict__ ei, const int* __restrict__ et) {
    int e = blockIdx.x * 256 + threadIdx.x;
    if (e >= NE) return;
    int dst = ei[NE + e];
    if (!g_need[dst]) return;
    int pos = atomicAdd(&g_cntr[dst], 1);
    if (pos < CAP)
        g_ebuf[(size_t)dst * CAP + pos] = ei[e] * N_REL + et[e];
}

// ---------------- K3: {di,sj} for all (node,rel)  (FFMA2 packed over f) ----------------
// di[n,t] = x[n]·(w_t @ att_t[:O]);  sj[n,t] = x[n]·(w_t @ att_t[O:])
__global__ void dsj_k(const int* __restrict__ x_ids, const float* __restrict__ emb,
                      const float* __restrict__ att) {
    __shared__ float xs[128 * EMB];      // 16 KB
    __shared__ float swa1[N_REL * EMB];  // w@att(:,0:32)  per (r,f)
    __shared__ float swa2[N_REL * EMB];  // w@att(:,32:64)
    int tid = threadIdx.x;
    int n0 = blockIdx.x * 128;

    {   // per-block wa: thread=(r,f)
        int r = tid >> 5, f = tid & 31;
        const float4* wr = (const float4*)(g_w + (r * EMB + f) * OUT);
        const float* a1 = att + r * 64;
        const float* a2 = a1 + 32;
        float s1 = 0.f, s2 = 0.f;
        #pragma unroll
        for (int q = 0; q < 8; q++) {
            float4 wv = wr[q];
            s1 += wv.x * __ldg(a1 + 4 * q)     + wv.y * __ldg(a1 + 4 * q + 1)
                + wv.z * __ldg(a1 + 4 * q + 2) + wv.w * __ldg(a1 + 4 * q + 3);
            s2 += wv.x * __ldg(a2 + 4 * q)     + wv.y * __ldg(a2 + 4 * q + 1)
                + wv.z * __ldg(a2 + 4 * q + 2) + wv.w * __ldg(a2 + 4 * q + 3);
        }
        swa1[r * EMB + f] = s1;
        swa2[r * EMB + f] = s2;
    }

    for (int idx = tid; idx < 128 * EMB; idx += 256) {
        int nl = idx >> 5, f = idx & 31;
        int n = n0 + nl;
        xs[idx] = (n < N_NODE) ? emb[(size_t)x_ids[n] * EMB + f] : 0.f;
    }
    __syncthreads();

    int nl = tid >> 1;
    int rbase = (tid & 1) * 4;
    int n = n0 + nl;
    if (n < N_NODE) {
        const ull* xp = (const ull*)(xs + (nl << 5));
        ull xv[16];
        #pragma unroll
        for (int q = 0; q < 16; q++) xv[q] = xp[q];
        #pragma unroll
        for (int k = 0; k < 4; k++) {
            int rr = rbase + k;
            const ull* w1p = (const ull*)(swa1 + rr * EMB);
            const ull* w2p = (const ull*)(swa2 + rr * EMB);
            ull aD = 0ULL, aS = 0ULL;
            #pragma unroll
            for (int q = 0; q < 16; q++) {
                aD = fma2(xv[q], w1p[q], aD);
                aS = fma2(xv[q], w2p[q], aS);
            }
            g_dsj[(size_t)n * N_REL + rr] = make_float2(fold2(aD), fold2(aS));
        }
    }
}

// ---------------- K4: per-node aggregation in EMBEDDING space + fused transform ----------------
// v_t = sum_e ex_e * x[src_e];  h = relu( sum_t (v_t/den_t)@w_t + x@root + bias )
__global__ void nodeagg_k(const int* __restrict__ x_ids, const float* __restrict__ emb,
                          const float* __restrict__ root, const float* __restrict__ bias) {
    __shared__ float swt[N_REL * EMB * OUT];  // 32 KB  w_t[f][o]
    __shared__ float sroot[EMB * OUT];        // 4 KB
    __shared__ int   sst[8][CAP];             // 4 KB  cached src*8+t
    __shared__ float sw[8][CAP];              // 4 KB  cached ex

    int tid = threadIdx.x;
    int wid = tid >> 5, lane = tid & 31;
    for (int i = tid; i < N_REL * EMB * OUT; i += 256) swt[i] = g_w[i];
    for (int i = tid; i < EMB * OUT; i += 256) sroot[i] = root[i];
    __syncthreads();

    int widx = blockIdx.x * 8 + wid;
    if (widx >= g_ncnt) return;
    int n   = g_nlist[widx];
    int deg = g_cntr[n];
    if (deg > CAP) deg = CAP;
    const int* ebase = g_ebuf + (size_t)n * CAP;

    // lanes 0..7 hold di[t] for this node
    float dv = 0.f;
    if (lane < N_REL) dv = g_dsj[n * N_REL + lane].x;

    // ---- phase 1: lane-parallel ex + per-relation denominators ----
    float pden[N_REL];
    #pragma unroll
    for (int t8 = 0; t8 < N_REL; t8++) pden[t8] = 0.f;

    for (int c = 0; c < deg; c += 32) {
        int j = c + lane;
        bool v = (j < deg);
        int st = 0;
        float ex = 0.f;
        int t = 0;
        if (v) {
            st = __ldg(&ebase[j]);
            t = st & 7;
        }
        float di = __shfl_sync(0xffffffffu, dv, t);
        if (v) {
            float sj = __ldg(&((const float*)g_dsj)[2 * st + 1]);
            float s = di + sj;
            s = (s > 0.f) ? s : 0.2f * s;
            ex = __expf(s);
            sst[wid][j] = st;
            sw[wid][j] = ex;
        }
        #pragma unroll
        for (int t8 = 0; t8 < N_REL; t8++)
            pden[t8] += (v && t == t8) ? ex : 0.f;
    }

    float rden[N_REL];
    #pragma unroll
    for (int t8 = 0; t8 < N_REL; t8++) {
        float s = pden[t8];
        #pragma unroll
        for (int o = 16; o > 0; o >>= 1) s += __shfl_xor_sync(0xffffffffu, s, o);
        rden[t8] = 1.f / (s + 1e-16f);
    }
    __syncwarp();

    // ---- phase 2: accumulate v_t in EMBEDDING space (lane = f) ----
    float v[N_REL];
    #pragma unroll
    for (int t8 = 0; t8 < N_REL; t8++) v[t8] = 0.f;

    #pragma unroll 4
    for (int j = 0; j < deg; j++) {
        int stj  = sst[wid][j];
        float exj = sw[wid][j];
        int src = stj >> 3;
        int t   = stj & 7;
        int xsrc = __ldg(x_ids + src);
        float xv = __ldg(emb + (size_t)xsrc * EMB + lane);   // 128B coalesced, L2-resident
        float m = xv * exj;
        #pragma unroll
        for (int t8 = 0; t8 < N_REL; t8++)
            v[t8] += (t == t8) ? m : 0.f;
    }

    // normalize
    #pragma unroll
    for (int t8 = 0; t8 < N_REL; t8++) v[t8] *= rden[t8];

    // ---- fused transform: acc[o] = bias[o] + sum_t sum_f v_t[f] * w_t[f][o] ----
    float acc = __ldg(bias + lane);
    #pragma unroll
    for (int t8 = 0; t8 < N_REL; t8++) {
        float vt = v[t8];
        const float* wt = swt + t8 * EMB * OUT;
        #pragma unroll
        for (int f = 0; f < EMB; f++)
            acc += __shfl_sync(0xffffffffu, vt, f) * wt[f * OUT + lane];
    }

    // ---- + x@root, relu ----
    int xn = __ldg(x_ids + n);
    float xo = __ldg(emb + (size_t)xn * EMB + lane);
    #pragma unroll
    for (int f = 0; f < EMB; f++)
        acc += __shfl_sync(0xffffffffu, xo, f) * sroot[f * OUT + lane];
    g_h[n * OUT + lane] = fmaxf(acc, 0.f);
}

// ---------------- K5: MLP over (user,bundle) pairs ----------------
__global__ void mlp_k(const int* __restrict__ users, const int* __restrict__ bundles,
                      const float* __restrict__ W1, const float* __restrict__ b1,
                      const float* __restrict__ W2, const float* __restrict__ b2,
                      const float* __restrict__ W3, const float* __restrict__ b3,
                      const float* __restrict__ Wo, const float* __restrict__ bo,
                      float* __restrict__ out) {
    __shared__ float sW1[2 * OUT * H1];
    __shared__ float sW2[H1 * H2];
    __shared__ float sW3[H2 * H3];
    __shared__ float sWo[H3];
    __shared__ float sb1[H1], sb2[H2], sb3[H3];

    int tid = threadIdx.x;
    for (int i = tid; i < 2 * OUT * H1; i += 128) sW1[i] = W1[i];
    for (int i = tid; i < H1 * H2; i += 128) sW2[i] = W2[i];
    for (int i = tid; i < H2 * H3; i += 128) sW3[i] = W3[i];
    if (tid < H3) sWo[tid] = Wo[tid];
    if (tid < H1) sb1[tid] = b1[tid];
    if (tid < H2) sb2[tid] = b2[tid];
    if (tid < H3) sb3[tid] = b3[tid];
    __syncthreads();

    int b = blockIdx.x * 128 + tid;
    if (b >= BATCH) return;

    int nu = users[b], nb = bundles[b];
    float z[2 * OUT];
    const float4* hu = (const float4*)(g_h + (size_t)nu * OUT);
    const float4* hb = (const float4*)(g_h + (size_t)nb * OUT);
    #pragma unroll
    for (int k = 0; k < 8; k++) {
        float4 v = hu[k];
        z[4 * k] = v.x; z[4 * k + 1] = v.y; z[4 * k + 2] = v.z; z[4 * k + 3] = v.w;
    }
    #pragma unroll
    for (int k = 0; k < 8; k++) {
        float4 v = hb[k];
        z[32 + 4 * k] = v.x; z[32 + 4 * k + 1] = v.y; z[32 + 4 * k + 2] = v.z; z[32 + 4 * k + 3] = v.w;
    }

    float a1[H1];
    for (int j = 0; j < H1; j++) {
        float acc = sb1[j];
        #pragma unroll
        for (int k = 0; k < 2 * OUT; k++) acc += z[k] * sW1[k * H1 + j];
        a1[j] = fmaxf(acc, 0.f);
    }
    float a2[H2];
    for (int j = 0; j < H2; j++) {
        float acc = sb2[j];
        #pragma unroll
        for (int k = 0; k < H1; k++) acc += a1[k] * sW2[k * H2 + j];
        a2[j] = fmaxf(acc, 0.f);
    }
    float a3[H3];
    for (int j = 0; j < H3; j++) {
        float acc = sb3[j];
        #pragma unroll
        for (int k = 0; k < H2; k++) acc += a2[k] * sW3[k * H3 + j];
        a3[j] = fmaxf(acc, 0.f);
    }
    float o = __ldg(bo);
    #pragma unroll
    for (int k = 0; k < H3; k++) o += a3[k] * sWo[k];
    out[b] = o;
}

// ---------------- launch ----------------
extern "C" void kernel_launch(void* const* d_in, const int* in_sizes, int n_in,
                              void* d_out, int out_size) {
    const int*   x_ids      = (const int*)d_in[0];
    const int*   edge_index = (const int*)d_in[1];
    const int*   edge_type  = (const int*)d_in[2];
    const int*   users      = (const int*)d_in[3];
    const int*   bundles    = (const int*)d_in[4];
    const float* emb        = (const float*)d_in[5];
    const float* basis      = (const float*)d_in[6];
    const float* weight     = (const float*)d_in[7];
    const float* att        = (const float*)d_in[8];
    const float* root       = (const float*)d_in[9];
    const float* bias       = (const float*)d_in[10];
    const float* W1         = (const float*)d_in[11];
    const float* b1         = (const float*)d_in[12];
    const float* W2         = (const float*)d_in[13];
    const float* b2         = (const float*)d_in[14];
    const float* W3         = (const float*)d_in[15];
    const float* b3         = (const float*)d_in[16];
    const float* Wo         = (const float*)d_in[17];
    const float* bo         = (const float*)d_in[18];
    float* out = (float*)d_out;

    initbasis_k<<<32 + 256, 256>>>(weight, basis);                    // 0
    mark_k<<<(2 * BATCH + 255) / 256, 256>>>(users, bundles);         // 1
    fill_k<<<(NE + 255) / 256, 256>>>(edge_index, edge_type);         // 2
    dsj_k<<<(N_NODE + 127) / 128, 256>>>(x_ids, emb, att);            // 3  <- profiled
    nodeagg_k<<<(2 * BATCH + 7) / 8, 256>>>(x_ids, emb, root, bias);  // 4
    mlp_k<<<BATCH / 128, 128>>>(users, bundles,
                                W1, b1, W2, b2, W3, b3, Wo, bo, out); // 5
}

// round 15
// speedup vs baseline: 1.8011x; 1.1710x over previous
#include <cuda_runtime.h>
#include <cuda_bf16.h>

#define N_NODE   100000
#define N_REL    8
#define EMB      32
#define OUT      32
#define NE       1600000
#define BATCH    16384
#define H1       64
#define H2       32
#define H3       16
#define CAP      128   // fixed bucket capacity per node (P(deg>128) ~ 1e-50)

typedef unsigned long long ull;

// ---------------- scratch (static device globals; no allocation) ----------------
__device__ float  g_w[N_REL * EMB * OUT];        // relation weights w[r][f][o]
__device__ float2 g_dsj[N_NODE * N_REL];         // {di, sj} per (node,rel)
__device__ float  g_h[N_NODE * OUT];             // final node features (needed rows only)
__device__ int    g_need[N_NODE];
__device__ int    g_cntr[N_NODE];                // bucket cursor / degree
__device__ int    g_nlist[N_NODE];               // compact list of needed nodes
__device__ int    g_ebuf[(size_t)N_NODE * CAP];  // fixed-stride buckets
__device__ int    g_ncnt;

// packed f32x2 ops (Blackwell)
__device__ __forceinline__ ull fma2(ull a, ull b, ull c) {
    ull d;
    asm("fma.rn.f32x2 %0, %1, %2, %3;" : "=l"(d) : "l"(a), "l"(b), "l"(c));
    return d;
}
__device__ __forceinline__ float fold2(ull a) {
    float lo, hi;
    asm("mov.b64 {%0,%1}, %2;" : "=f"(lo), "=f"(hi) : "l"(a));
    return lo + hi;
}
__device__ __forceinline__ ull pack2(float lo, float hi) {
    ull d;
    asm("mov.b64 %0, {%1,%2};" : "=l"(d) : "f"(lo), "f"(hi));
    return d;
}

// ---------------- K0: fused basis GEMM (blocks 0..31) + scratch zeroing ----------------
__global__ void initbasis_k(const float* __restrict__ weight, const float* __restrict__ basis) {
    int b = blockIdx.x;
    int tid = threadIdx.x;
    if (b < 32) {
        int gid = b * 256 + tid;
        int r = gid >> 10, fo = gid & 1023;
        float acc = 0.f;
        #pragma unroll
        for (int k = 0; k < 30; k++)
            acc += __ldg(weight + r * 30 + k) * __ldg(basis + k * 1024 + fo);
        g_w[r * 1024 + fo] = acc;
        if (gid == 0) g_ncnt = 0;
    } else {
        int i = (b - 32) * 256 + tid;
        int stride = (gridDim.x - 32) * 256;
        for (int j = i; j < N_NODE; j += stride) { g_need[j] = 0; g_cntr[j] = 0; }
    }
}

// ---------------- K1: mark needed dst nodes + compact list ----------------
__global__ void mark_k(const int* __restrict__ users, const int* __restrict__ bundles) {
    int i = blockIdx.x * blockDim.x + threadIdx.x;
    if (i >= 2 * BATCH) return;
    int u = (i < BATCH) ? users[i] : bundles[i - BATCH];
    if (atomicExch(&g_need[u], 1) == 0) {
        int p = atomicAdd(&g_ncnt, 1);
        g_nlist[p] = u;
    }
}

// ---------------- K2: single-pass bucket fill ----------------
__global__ void fill_k(const int* __restrict__ ei, const int* __restrict__ et) {
    int e = blockIdx.x * 256 + threadIdx.x;
    if (e >= NE) return;
    int dst = ei[NE + e];
    if (!g_need[dst]) return;
    int pos = atomicAdd(&g_cntr[dst], 1);
    if (pos < CAP)
        g_ebuf[(size_t)dst * CAP + pos] = ei[e] * N_REL + et[e];
}

// ---------------- K3: {di,sj} — persistent grid-stride, x in registers ----------------
// di[n,t] = x[n]·(w_t @ att_t[:O]);  sj[n,t] = x[n]·(w_t @ att_t[O:])
// thread slot = (node, rel-half): 2 threads per node, 4 rels each, no per-node syncs.
__global__ void dsj_k(const int* __restrict__ x_ids, const float* __restrict__ emb,
                      const float* __restrict__ att) {
    __shared__ float swa1[N_REL * EMB];  // w@att(:,0:32)  per (r,f)
    __shared__ float swa2[N_REL * EMB];  // w@att(:,32:64)
    int tid = threadIdx.x;

    {   // per-block wa prologue: thread=(r,f)
        int r = tid >> 5, f = tid & 31;
        const float4* wr = (const float4*)(g_w + (r * EMB + f) * OUT);
        const float* a1 = att + r * 64;
        const float* a2 = a1 + 32;
        float s1 = 0.f, s2 = 0.f;
        #pragma unroll
        for (int q = 0; q < 8; q++) {
            float4 wv = __ldg(wr + q);
            s1 += wv.x * __ldg(a1 + 4 * q)     + wv.y * __ldg(a1 + 4 * q + 1)
                + wv.z * __ldg(a1 + 4 * q + 2) + wv.w * __ldg(a1 + 4 * q + 3);
            s2 += wv.x * __ldg(a2 + 4 * q)     + wv.y * __ldg(a2 + 4 * q + 1)
                + wv.z * __ldg(a2 + 4 * q + 2) + wv.w * __ldg(a2 + 4 * q + 3);
        }
        swa1[r * EMB + f] = s1;
        swa2[r * EMB + f] = s2;
    }
    __syncthreads();

    int slot = blockIdx.x * 256 + tid;
    int nslots = gridDim.x * 256;

    for (int idx = slot; idx < 2 * N_NODE; idx += nslots) {
        int n = idx >> 1;
        int rbase = (idx & 1) * 4;
        // load x row into registers (8x LDG.128; sibling thread shares lines via L1)
        const float4* xr = (const float4*)(emb + (size_t)__ldg(x_ids + n) * EMB);
        ull xv[16];
        #pragma unroll
        for (int q = 0; q < 8; q++) {
            float4 v = __ldg(xr + q);
            xv[2 * q]     = pack2(v.x, v.y);
            xv[2 * q + 1] = pack2(v.z, v.w);
        }
        #pragma unroll
        for (int k = 0; k < 4; k++) {
            int rr = rbase + k;
            const ull* w1p = (const ull*)(swa1 + rr * EMB);
            const ull* w2p = (const ull*)(swa2 + rr * EMB);
            ull aD = 0ULL, aS = 0ULL;
            #pragma unroll
            for (int q = 0; q < 16; q++) {
                aD = fma2(xv[q], w1p[q], aD);
                aS = fma2(xv[q], w2p[q], aS);
            }
            g_dsj[(size_t)n * N_REL + rr] = make_float2(fold2(aD), fold2(aS));
        }
    }
}

// ---------------- K4: per-node aggregation in EMBEDDING space + fused transform ----------------
__global__ void nodeagg_k(const int* __restrict__ x_ids, const float* __restrict__ emb,
                          const float* __restrict__ root, const float* __restrict__ bias) {
    __shared__ float swt[N_REL * EMB * OUT];  // 32 KB  w_t[f][o]
    __shared__ float sroot[EMB * OUT];        // 4 KB
    __shared__ int   sst[8][CAP];             // cached xsrc*8+t (translated!)
    __shared__ float sw[8][CAP];              // cached ex

    int tid = threadIdx.x;
    int wid = tid >> 5, lane = tid & 31;
    for (int i = tid; i < N_REL * EMB * OUT; i += 256) swt[i] = g_w[i];
    for (int i = tid; i < EMB * OUT; i += 256) sroot[i] = root[i];
    __syncthreads();

    int widx = blockIdx.x * 8 + wid;
    if (widx >= g_ncnt) return;
    int n   = g_nlist[widx];
    int deg = g_cntr[n];
    if (deg > CAP) deg = CAP;
    const int* ebase = g_ebuf + (size_t)n * CAP;

    float dv = 0.f;
    if (lane < N_REL) dv = g_dsj[n * N_REL + lane].x;

    // ---- phase 1: lane-parallel ex + denominators + x_ids translation ----
    float pden[N_REL];
    #pragma unroll
    for (int t8 = 0; t8 < N_REL; t8++) pden[t8] = 0.f;

    for (int c = 0; c < deg; c += 32) {
        int j = c + lane;
        bool v = (j < deg);
        int st = 0;
        float ex = 0.f;
        int t = 0;
        if (v) {
            st = __ldg(&ebase[j]);
            t = st & 7;
        }
        float di = __shfl_sync(0xffffffffu, dv, t);
        if (v) {
            float sj = __ldg(&((const float*)g_dsj)[2 * st + 1]);
            float s = di + sj;
            s = (s > 0.f) ? s : 0.2f * s;
            ex = __expf(s);
            int xsrc = __ldg(x_ids + (st >> 3));        // translate now (L2-resident)
            sst[wid][j] = (xsrc << 3) | t;
            sw[wid][j] = ex;
        }
        #pragma unroll
        for (int t8 = 0; t8 < N_REL; t8++)
            pden[t8] += (v && t == t8) ? ex : 0.f;
    }

    float rden[N_REL];
    #pragma unroll
    for (int t8 = 0; t8 < N_REL; t8++) {
        float s = pden[t8];
        #pragma unroll
        for (int o = 16; o > 0; o >>= 1) s += __shfl_xor_sync(0xffffffffu, s, o);
        rden[t8] = 1.f / (s + 1e-16f);
    }
    __syncwarp();

    // ---- phase 2: accumulate v_t in embedding space (lane = f), single load per edge ----
    float v[N_REL];
    #pragma unroll
    for (int t8 = 0; t8 < N_REL; t8++) v[t8] = 0.f;

    #pragma unroll 4
    for (int j = 0; j < deg; j++) {
        int stj  = sst[wid][j];
        float exj = sw[wid][j];
        float xv = __ldg(emb + (size_t)(stj >> 3) * EMB + lane);  // coalesced 128B
        float m = xv * exj;
        int t = stj & 7;
        #pragma unroll
        for (int t8 = 0; t8 < N_REL; t8++)
            v[t8] += (t == t8) ? m : 0.f;
    }

    #pragma unroll
    for (int t8 = 0; t8 < N_REL; t8++) v[t8] *= rden[t8];

    // ---- fused transform: acc[o] = bias[o] + sum_t sum_f v_t[f] * w_t[f][o] ----
    float acc = __ldg(bias + lane);
    #pragma unroll
    for (int t8 = 0; t8 < N_REL; t8++) {
        float vt = v[t8];
        const float* wt = swt + t8 * EMB * OUT;
        #pragma unroll
        for (int f = 0; f < EMB; f++)
            acc += __shfl_sync(0xffffffffu, vt, f) * wt[f * OUT + lane];
    }

    // ---- + x@root, relu ----
    int xn = __ldg(x_ids + n);
    float xo = __ldg(emb + (size_t)xn * EMB + lane);
    #pragma unroll
    for (int f = 0; f < EMB; f++)
        acc += __shfl_sync(0xffffffffu, xo, f) * sroot[f * OUT + lane];
    g_h[n * OUT + lane] = fmaxf(acc, 0.f);
}

// ---------------- K5: MLP, streamed a1 (low register pressure) ----------------
__global__ void mlp_k(const int* __restrict__ users, const int* __restrict__ bundles,
                      const float* __restrict__ W1, const float* __restrict__ b1,
                      const float* __restrict__ W2, const float* __restrict__ b2,
                      const float* __restrict__ W3, const float* __restrict__ b3,
                      const float* __restrict__ Wo, const float* __restrict__ bo,
                      float* __restrict__ out) {
    __shared__ float sW1[2 * OUT * H1];
    __shared__ float sW2[H1 * H2];
    __shared__ float sW3[H2 * H3];
    __shared__ float sWo[H3];
    __shared__ float sb1[H1], sb2[H2], sb3[H3];

    int tid = threadIdx.x;   // 64 threads
    for (int i = tid; i < 2 * OUT * H1; i += 64) sW1[i] = W1[i];
    for (int i = tid; i < H1 * H2; i += 64) sW2[i] = W2[i];
    for (int i = tid; i < H2 * H3; i += 64) sW3[i] = W3[i];
    if (tid < H3) sWo[tid] = Wo[tid];
    if (tid < H1) sb1[tid] = b1[tid];
    if (tid < H2) sb2[tid] = b2[tid];
    if (tid < H3) sb3[tid] = b3[tid];
    __syncthreads();

    int b = blockIdx.x * 64 + tid;
    if (b >= BATCH) return;

    int nu = users[b], nb = bundles[b];
    float z[2 * OUT];
    const float4* hu = (const float4*)(g_h + (size_t)nu * OUT);
    const float4* hb = (const float4*)(g_h + (size_t)nb * OUT);
    #pragma unroll
    for (int k = 0; k < 8; k++) {
        float4 v = __ldg(hu + k);
        z[4 * k] = v.x; z[4 * k + 1] = v.y; z[4 * k + 2] = v.z; z[4 * k + 3] = v.w;
    }
    #pragma unroll
    for (int k = 0; k < 8; k++) {
        float4 v = __ldg(hb + k);
        z[32 + 4 * k] = v.x; z[32 + 4 * k + 1] = v.y; z[32 + 4 * k + 2] = v.z; z[32 + 4 * k + 3] = v.w;
    }

    // stage 1+2 streamed: never materialize a1[]
    float a2[H2];
    #pragma unroll
    for (int m = 0; m < H2; m++) a2[m] = sb2[m];
    for (int j = 0; j < H1; j++) {
        float t = sb1[j];
        #pragma unroll
        for (int k = 0; k < 2 * OUT; k++) t += z[k] * sW1[k * H1 + j];
        t = fmaxf(t, 0.f);
        #pragma unroll
        for (int m = 0; m < H2; m++) a2[m] += t * sW2[j * H2 + m];
    }
    #pragma unroll
    for (int m = 0; m < H2; m++) a2[m] = fmaxf(a2[m], 0.f);

    // stage 3 streamed
    float a3[H3];
    #pragma unroll
    for (int m = 0; m < H3; m++) a3[m] = sb3[m];
    for (int j = 0; j < H2; j++) {
        float t = a2[j];
        #pragma unroll
        for (int m = 0; m < H3; m++) a3[m] += t * sW3[j * H3 + m];
    }
    float o = __ldg(bo);
    #pragma unroll
    for (int k = 0; k < H3; k++) o += fmaxf(a3[k], 0.f) * sWo[k];
    out[b] = o;
}

// ---------------- launch ----------------
extern "C" void kernel_launch(void* const* d_in, const int* in_sizes, int n_in,
                              void* d_out, int out_size) {
    const int*   x_ids      = (const int*)d_in[0];
    const int*   edge_index = (const int*)d_in[1];
    const int*   edge_type  = (const int*)d_in[2];
    const int*   users      = (const int*)d_in[3];
    const int*   bundles    = (const int*)d_in[4];
    const float* emb        = (const float*)d_in[5];
    const float* basis      = (const float*)d_in[6];
    const float* weight     = (const float*)d_in[7];
    const float* att        = (const float*)d_in[8];
    const float* root       = (const float*)d_in[9];
    const float* bias       = (const float*)d_in[10];
    const float* W1         = (const float*)d_in[11];
    const float* b1         = (const float*)d_in[12];
    const float* W2         = (const float*)d_in[13];
    const float* b2         = (const float*)d_in[14];
    const float* W3         = (const float*)d_in[15];
    const float* b3         = (const float*)d_in[16];
    const float* Wo         = (const float*)d_in[17];
    const float* bo         = (const float*)d_in[18];
    float* out = (float*)d_out;

    initbasis_k<<<32 + 256, 256>>>(weight, basis);                    // 0
    mark_k<<<(2 * BATCH + 255) / 256, 256>>>(users, bundles);         // 1
    fill_k<<<(NE + 255) / 256, 256>>>(edge_index, edge_type);         // 2
    dsj_k<<<296, 256>>>(x_ids, emb, att);                             // 3  <- profiled
    nodeagg_k<<<(2 * BATCH + 7) / 8, 256>>>(x_ids, emb, root, bias);  // 4
    mlp_k<<<BATCH / 64, 64>>>(users, bundles,
                              W1, b1, W2, b2, W3, b3, Wo, bo, out);   // 5
}